// round 12
// baseline (speedup 1.0000x reference)
#include <cuda_runtime.h>
#include <cuda_pipeline_primitives.h>

// x (B=8, S=4096, D=1024) fp32. Stats from sequential scan over D of x[0]:
//   m_i = (m_{i-1} + d_i)/i ;  v += (d_i - m_i)^2 ;  var = v/(D-1)
// Scan state decays by prod(1/i): 16-step warm-up makes per-segment restarts
// exact to ~1e-20, so the scan parallelizes over all 256 threads.
// One block per row; b=0 normalized from the smem copy (read exactly once).
// R12: x[0] row ALSO loaded via cp.async (group 0, linear smem — float4/thread
// LDS is naturally conflict-free), 4-deep cp.async ring for b=1..4 prefetched
// before the scan; no barriers in the stream loop (own 16B slice only).
// Occupancy invariant: regs ~32, smem ~20KB -> 8 CTAs/SM (reg-limited).

#define S_DIM 4096
#define D_DIM 1024
#define EPSV  1e-5f
#define WARM  16

__global__ __launch_bounds__(256)
void ln_fused_kernel(const float* __restrict__ x,
                     const float* __restrict__ alpha,
                     const float* __restrict__ beta,
                     float* __restrict__ out,
                     int B) {
    __shared__ __align__(16) float row[D_DIM];          // linear row of x[0]
    __shared__ __align__(16) float stage[4][D_DIM];     // cp.async ring (16KB)
    __shared__ float s_part[8];
    __shared__ float s_stats[2];

    const int s   = blockIdx.x;
    const int tid = threadIdx.x;
    const size_t rowOff4 = (size_t)s * (D_DIM / 4) + tid;   // float4 index
    const float4* __restrict__ xf = (const float4*)x;

    const bool fast = (B == 8);
    if (fast) {
        // group 0: the stats row itself (drained by wait_prior(4) below)
        __pipeline_memcpy_async(&row[tid * 4], xf + rowOff4, 16);
        __pipeline_commit();
        // groups 1..4: batches b=1..4 (stay in flight through the scan)
#pragma unroll
        for (int bb = 1; bb <= 4; ++bb) {
            __pipeline_memcpy_async(&stage[bb - 1][tid * 4],
                                    xf + (size_t)bb * S_DIM * (D_DIM / 4) + rowOff4, 16);
            __pipeline_commit();
        }
    } else {
        float4 v = __ldg(xf + rowOff4);
        *(float4*)&row[tid * 4] = v;
    }

    // alpha/beta early — their latency rides the prologue
    const float4 a = __ldg(((const float4*)alpha) + tid);
    const float4 b = __ldg(((const float4*)beta)  + tid);

    if (fast) __pipeline_wait_prior(4);     // row group done; ring still flying
    __syncthreads();

    // ---- Phase 2: all-thread segment-parallel scan (4 elems/thread) ----
    {
        const int start = tid * 4;
        float m = 0.0f, v = 0.0f;

        if (start >= WARM) {
            // 16-step warm-up, consumed in float4 chunks (4 regs live, not 16)
#pragma unroll
            for (int c = 0; c < 4; ++c) {
                const int i0 = start - WARM + c * 4;
                float4 w = *(const float4*)&row[i0];
                m = fmaf(m, __fdividef(1.0f, (float)(i0 + 1)), w.x * __fdividef(1.0f, (float)(i0 + 1)));
                m = fmaf(m, __fdividef(1.0f, (float)(i0 + 2)), w.y * __fdividef(1.0f, (float)(i0 + 2)));
                m = fmaf(m, __fdividef(1.0f, (float)(i0 + 3)), w.z * __fdividef(1.0f, (float)(i0 + 3)));
                m = fmaf(m, __fdividef(1.0f, (float)(i0 + 4)), w.w * __fdividef(1.0f, (float)(i0 + 4)));
            }
        } else {
            // tids 0..3: exact scan from the row start
            for (int j = start; j > 0; --j) {
                int idx = start - j;
                float r = __fdividef(1.0f, (float)(idx + 1));
                m = fmaf(m, r, row[idx] * r);
            }
        }

        float4 d4 = *(const float4*)&row[start];     // one conflict-free LDS.128
        {
            float r0 = __fdividef(1.0f, (float)(start + 1));
            m = fmaf(m, r0, d4.x * r0); float t0 = d4.x - m; v = fmaf(t0, t0, v);
            float r1 = __fdividef(1.0f, (float)(start + 2));
            m = fmaf(m, r1, d4.y * r1); float t1 = d4.y - m; v = fmaf(t1, t1, v);
            float r2 = __fdividef(1.0f, (float)(start + 3));
            m = fmaf(m, r2, d4.z * r2); float t2 = d4.z - m; v = fmaf(t2, t2, v);
            float r3 = __fdividef(1.0f, (float)(start + 4));
            m = fmaf(m, r3, d4.w * r3); float t3 = d4.w - m; v = fmaf(t3, t3, v);
        }
        if (tid == 255) s_stats[0] = m;

#pragma unroll
        for (int o = 16; o; o >>= 1)
            v += __shfl_xor_sync(0xffffffffu, v, o);
        if ((tid & 31) == 0) s_part[tid >> 5] = v;
        __syncthreads();
        if (tid == 0) {
            float vt = s_part[0] + s_part[1] + s_part[2] + s_part[3]
                     + s_part[4] + s_part[5] + s_part[6] + s_part[7];
            s_stats[1] = rsqrtf(vt / (float)(D_DIM - 1) + EPSV);
        }
    }
    __syncthreads();

    const float m  = s_stats[0];
    const float rs = s_stats[1];

    // ---- Phase 3a: b = 0 from the smem copy (one LDS.128) ----
    {
        float4 xv = *(const float4*)&row[tid * 4];
        float4 ov;
        ov.x = fmaf((xv.x - m) * rs, a.x, b.x);
        ov.y = fmaf((xv.y - m) * rs, a.y, b.y);
        ov.z = fmaf((xv.z - m) * rs, a.z, b.z);
        ov.w = fmaf((xv.w - m) * rs, a.w, b.w);
        __stcs(((float4*)out) + rowOff4, ov);
    }

    // ---- Phase 3b: stream b = 1..7 through the 4-deep cp.async ring ----
    if (fast) {
        // ring groups pending newer than bb at consume = min(3, 7-bb)
#pragma unroll
        for (int bb = 1; bb < 8; ++bb) {
            if      (bb <= 4) __pipeline_wait_prior(3);
            else if (bb == 5) __pipeline_wait_prior(2);
            else if (bb == 6) __pipeline_wait_prior(1);
            else              __pipeline_wait_prior(0);

            float4 xv = *(const float4*)&stage[(bb - 1) & 3][tid * 4];

            if (bb + 4 < 8) {   // refill the slot just consumed (own slice only)
                __pipeline_memcpy_async(&stage[(bb - 1) & 3][tid * 4],
                                        xf + (size_t)(bb + 4) * S_DIM * (D_DIM / 4) + rowOff4, 16);
                __pipeline_commit();
            }

            float4 ov;
            ov.x = fmaf((xv.x - m) * rs, a.x, b.x);
            ov.y = fmaf((xv.y - m) * rs, a.y, b.y);
            ov.z = fmaf((xv.z - m) * rs, a.z, b.z);
            ov.w = fmaf((xv.w - m) * rs, a.w, b.w);
            __stcs(((float4*)out) + (size_t)bb * S_DIM * (D_DIM / 4) + rowOff4, ov);
        }
    } else {
        for (int bb = 1; bb < B; ++bb) {
            size_t idx = (size_t)bb * S_DIM * (D_DIM / 4) + rowOff4;
            float4 xv = __ldcs(xf + idx);
            float4 ov;
            ov.x = fmaf((xv.x - m) * rs, a.x, b.x);
            ov.y = fmaf((xv.y - m) * rs, a.y, b.y);
            ov.z = fmaf((xv.z - m) * rs, a.z, b.z);
            ov.w = fmaf((xv.w - m) * rs, a.w, b.w);
            __stcs(((float4*)out) + idx, ov);
        }
    }
}

extern "C" void kernel_launch(void* const* d_in, const int* in_sizes, int n_in,
                              void* d_out, int out_size) {
    const float* x     = (const float*)d_in[0];
    const float* alpha = (const float*)d_in[1];
    const float* beta  = (const float*)d_in[2];
    float*       out   = (float*)d_out;

    const int B = in_sizes[0] / (S_DIM * D_DIM);

    ln_fused_kernel<<<S_DIM, 256>>>(x, alpha, beta, out, B);
}

// round 14
// speedup vs baseline: 1.0007x; 1.0007x over previous
#include <cuda_runtime.h>
#include <cuda_pipeline_primitives.h>

// x (B=8, S=4096, D=1024) fp32. Stats from sequential scan over D of x[0]:
//   m_i = (m_{i-1} + d_i)/i ;  v += (d_i - m_i)^2 ;  var = v/(D-1)
// Scan state decays by prod(1/i): 16-step warm-up makes per-segment restarts
// exact to ~1e-20, so the scan parallelizes over all 256 threads.
// One block per row; b=0 normalized from the smem copy (read exactly once).
// Stream loads 4-deep cp.async ring (b=1..4 prefetched before the scan);
// each thread consumes only its own 16B slice -> no barriers in stream loop.
// Occupancy invariant: regs ~32, smem ~21KB (8 CTAs/SM, reg-limited).
// FINAL (R10 config): kernel 36.06us, DRAM 74.3%, 7.43 TB/s effective.

#define S_DIM 4096
#define D_DIM 1024
#define EPSV  1e-5f
#define WARM  16

__global__ __launch_bounds__(256)
void ln_fused_kernel(const float* __restrict__ x,
                     const float* __restrict__ alpha,
                     const float* __restrict__ beta,
                     float* __restrict__ out,
                     int B) {
    __shared__ float row[D_DIM + D_DIM / 32];           // swizzled row of x[0]
    __shared__ __align__(16) float stage[4][D_DIM];     // cp.async ring (16KB)
    __shared__ float s_part[8];
    __shared__ float s_stats[2];

    const int s   = blockIdx.x;
    const int tid = threadIdx.x;
    const size_t rowOff4 = (size_t)s * (D_DIM / 4) + tid;   // float4 index
    const float4* __restrict__ xf = (const float4*)x;

    const bool fast = (B == 8);
    if (fast) {
        // prefetch b=1..4 before the scan — latency hides under the prologue
#pragma unroll
        for (int bb = 1; bb <= 4; ++bb) {
            __pipeline_memcpy_async(&stage[bb - 1][tid * 4],
                                    xf + (size_t)bb * S_DIM * (D_DIM / 4) + rowOff4, 16);
            __pipeline_commit();
        }
    }

    // alpha/beta early — their latency also rides the prologue
    const float4 a = __ldg(((const float4*)alpha) + tid);
    const float4 b = __ldg(((const float4*)beta)  + tid);

    // ---- Phase 1: coalesced load of x[0,s,:] into swizzled smem ----
    {
        float4 v = __ldg(xf + rowOff4);
        int base = tid * 4;
        int o = base + (base >> 5);
        row[o]   = v.x; row[o+1] = v.y;
        row[o+2] = v.z; row[o+3] = v.w;
    }
    __syncthreads();

    // ---- Phase 2: all-thread segment-parallel scan (4 elems/thread) ----
    {
        const int start = tid * 4;
        const int wu    = (start < WARM) ? start : WARM;
        float m = 0.0f, v = 0.0f;

        for (int j = wu; j > 0; --j) {
            int idx = start - j;
            float d = row[idx + (idx >> 5)];
            float r = __fdividef(1.0f, (float)(idx + 1));
            m = fmaf(m, r, d * r);
        }
#pragma unroll
        for (int j = 0; j < 4; ++j) {
            int idx = start + j;
            float d = row[idx + (idx >> 5)];
            float r = __fdividef(1.0f, (float)(idx + 1));
            m = fmaf(m, r, d * r);               // (m + d)/i
            float t = d - m;
            v = fmaf(t, t, v);
        }
        if (tid == 255) s_stats[0] = m;

#pragma unroll
        for (int o = 16; o; o >>= 1)
            v += __shfl_xor_sync(0xffffffffu, v, o);
        if ((tid & 31) == 0) s_part[tid >> 5] = v;
        __syncthreads();
        if (tid == 0) {
            float vt = s_part[0] + s_part[1] + s_part[2] + s_part[3]
                     + s_part[4] + s_part[5] + s_part[6] + s_part[7];
            s_stats[1] = rsqrtf(vt / (float)(D_DIM - 1) + EPSV);
        }
    }
    __syncthreads();

    const float m  = s_stats[0];
    const float rs = s_stats[1];

    // ---- Phase 3a: b = 0 from the smem copy ----
    {
        int base = tid * 4;
        int o = base + (base >> 5);
        float4 ov;
        ov.x = fmaf((row[o]   - m) * rs, a.x, b.x);
        ov.y = fmaf((row[o+1] - m) * rs, a.y, b.y);
        ov.z = fmaf((row[o+2] - m) * rs, a.z, b.z);
        ov.w = fmaf((row[o+3] - m) * rs, a.w, b.w);
        __stcs(((float4*)out) + rowOff4, ov);
    }

    // ---- Phase 3b: stream b = 1..7 through the 4-deep cp.async ring ----
    if (fast) {
        // commits: b1..b4 pre-scan, refills b5,b6,b7 at bb=1,2,3.
        // pending groups newer than bb at consume = 4+min(bb-1,3)-bb.
#pragma unroll
        for (int bb = 1; bb < 8; ++bb) {
            if      (bb <= 4) __pipeline_wait_prior(3);
            else if (bb == 5) __pipeline_wait_prior(2);
            else if (bb == 6) __pipeline_wait_prior(1);
            else              __pipeline_wait_prior(0);

            float4 xv = *(const float4*)&stage[(bb - 1) & 3][tid * 4];

            if (bb + 4 < 8) {   // refill the slot just consumed (own slice only)
                __pipeline_memcpy_async(&stage[(bb - 1) & 3][tid * 4],
                                        xf + (size_t)(bb + 4) * S_DIM * (D_DIM / 4) + rowOff4, 16);
                __pipeline_commit();
            }

            float4 ov;
            ov.x = fmaf((xv.x - m) * rs, a.x, b.x);
            ov.y = fmaf((xv.y - m) * rs, a.y, b.y);
            ov.z = fmaf((xv.z - m) * rs, a.z, b.z);
            ov.w = fmaf((xv.w - m) * rs, a.w, b.w);
            __stcs(((float4*)out) + (size_t)bb * S_DIM * (D_DIM / 4) + rowOff4, ov);
        }
    } else {
        for (int bb = 1; bb < B; ++bb) {
            size_t idx = (size_t)bb * S_DIM * (D_DIM / 4) + rowOff4;
            float4 xv = __ldcs(xf + idx);
            float4 ov;
            ov.x = fmaf((xv.x - m) * rs, a.x, b.x);
            ov.y = fmaf((xv.y - m) * rs, a.y, b.y);
            ov.z = fmaf((xv.z - m) * rs, a.z, b.z);
            ov.w = fmaf((xv.w - m) * rs, a.w, b.w);
            __stcs(((float4*)out) + idx, ov);
        }
    }
}

extern "C" void kernel_launch(void* const* d_in, const int* in_sizes, int n_in,
                              void* d_out, int out_size) {
    const float* x     = (const float*)d_in[0];
    const float* alpha = (const float*)d_in[1];
    const float* beta  = (const float*)d_in[2];
    float*       out   = (float*)d_out;

    const int B = in_sizes[0] / (S_DIM * D_DIM);

    ln_fused_kernel<<<S_DIM, 256>>>(x, alpha, beta, out, B);
}